// round 6
// baseline (speedup 1.0000x reference)
#include <cuda_runtime.h>
#include <cuda_bf16.h>
#include <cstdint>

#define CODES 1024
#define CDIM  256
#define HW    1024
#define NPIX  65536
#define NCHUNK 8            // 1024 codes / 128
#define NTILE  512          // 65536 px / 128

// ---------------- static scratch ----------------
__device__ __align__(1024) unsigned char g_wb[NCHUNK * 65536]; // bf16 B images (swizzled)
__device__ __align__(1024) unsigned char g_xb[NTILE * 65536];  // bf16 A images (swizzled)
__device__ float g_wsq[CODES];
__device__ float g_pmax[128];
__device__ float g_xx[NPIX];
__device__ float g_sx[NPIX];
__device__ int   g_cand[NPIX * 32];
__device__ int   g_cnt[NPIX];
__device__ int   g_idx[NPIX];
__device__ int   g_queue[NPIX];
__device__ int   g_qcnt;

// ---------------- helpers ----------------
__device__ __forceinline__ uint32_t smem_u32(const void *p) {
    uint32_t a;
    asm("{ .reg .u64 t; cvta.to.shared.u64 t, %1; cvt.u32.u64 %0, t; }" : "=r"(a) : "l"(p));
    return a;
}
__device__ __forceinline__ void cp16(uint32_t dst, const void *src) {
    asm volatile("cp.async.cg.shared.global [%0], [%1], 16;" :: "r"(dst), "l"(src) : "memory");
}
#define CP_COMMIT() asm volatile("cp.async.commit_group;" ::: "memory")
#define CP_WAIT1()  asm volatile("cp.async.wait_group 1;" ::: "memory")
#define CP_WAIT0()  asm volatile("cp.async.wait_group 0;" ::: "memory")

__device__ __forceinline__ uint32_t packbf(float lo, float hi) {
    uint32_t r;
    asm("cvt.rn.bf16x2.f32 %0, %1, %2;" : "=r"(r) : "f"(hi), "f"(lo));  // r = hi<<16 | lo
    return r;
}
// image layout: 128 rows x 256 bf16 k-major, rows of 512B = 32 16B-chunks,
// chunk swizzle: stored chunk index = chunk ^ (row & 7)  -> ldmatrix conflict-free
__device__ __forceinline__ uint32_t img_off(int row, int chunk) {
    return (uint32_t)row * 512u + (uint32_t)((chunk ^ (row & 7)) << 4);
}

__device__ __forceinline__ void ldsm_x4(uint32_t &r0, uint32_t &r1, uint32_t &r2, uint32_t &r3,
                                        uint32_t addr) {
    asm volatile("ldmatrix.sync.aligned.m8n8.x4.shared.b16 {%0,%1,%2,%3}, [%4];"
                 : "=r"(r0), "=r"(r1), "=r"(r2), "=r"(r3) : "r"(addr));
}
__device__ __forceinline__ void mma16816(float *d, uint32_t a0, uint32_t a1, uint32_t a2,
                                         uint32_t a3, uint32_t b0, uint32_t b1) {
    asm volatile("mma.sync.aligned.m16n8k16.row.col.f32.bf16.bf16.f32 "
                 "{%0,%1,%2,%3}, {%4,%5,%6,%7}, {%8,%9}, {%0,%1,%2,%3};"
                 : "+f"(d[0]), "+f"(d[1]), "+f"(d[2]), "+f"(d[3])
                 : "r"(a0), "r"(a1), "r"(a2), "r"(a3), "r"(b0), "r"(b1));
}

// =====================================================================
// prep_w: exact wsq, bf16 swizzled B images, per-block max|w|, zero queue
// grid 128 x 256 (8 codes/block, one warp per code)
// =====================================================================
__global__ void prep_w(const float *__restrict__ w) {
    __shared__ float wm[8];
    if (blockIdx.x == 0 && threadIdx.x == 0) g_qcnt = 0;
    int wid = threadIdx.x >> 5, lane = threadIdx.x & 31;
    int code = blockIdx.x * 8 + wid;
    const float *row = w + code * CDIM;
    float s = 0.f, pm = 0.f;
#pragma unroll
    for (int j = 0; j < 8; j++) {
        float v = row[lane + 32 * j];
        s = __fmaf_rn(v, v, s);
        pm = fmaxf(pm, fabsf(v));
    }
#pragma unroll
    for (int o = 16; o; o >>= 1) {
        s += __shfl_xor_sync(0xffffffffu, s, o);
        pm = fmaxf(pm, __shfl_xor_sync(0xffffffffu, pm, o));
    }
    if (lane == 0) { g_wsq[code] = s; wm[wid] = pm; }
    // bf16 image: lane owns 16B chunk (8 consecutive k), chunk index = lane
    float f[8];
#pragma unroll
    for (int j = 0; j < 8; j++) f[j] = row[lane * 8 + j];
    uint4 v;
    v.x = packbf(f[0], f[1]); v.y = packbf(f[2], f[3]);
    v.z = packbf(f[4], f[5]); v.w = packbf(f[6], f[7]);
    int chunk = code >> 7, lr = code & 127;
    *(uint4 *)(g_wb + chunk * 65536 + img_off(lr, lane)) = v;
    __syncthreads();
    if (threadIdx.x == 0) {
        float m = 0.f;
        for (int i = 0; i < 8; i++) m = fmaxf(m, wm[i]);
        g_pmax[blockIdx.x] = m;
    }
}

// =====================================================================
// prep_x: per 128-pixel tile: transpose+convert x -> bf16 swizzled A image,
//         exact sequential xx and sum|x|.  grid 512 x 256.
// =====================================================================
#define XP 130
__global__ __launch_bounds__(256) void prep_x(const float *__restrict__ x) {
    extern __shared__ float sm[];
    const int tile = blockIdx.x;
    const int b = tile >> 3, hw0 = (tile & 7) * 128;
    const int tid = threadIdx.x;
    unsigned char *dst = g_xb + (size_t)tile * 65536;
    float xxa = 0.f, sxa = 0.f;

    for (int h = 0; h < 2; h++) {
        const float *src = x + (size_t)b * CDIM * HW + (size_t)(h * 128) * HW + hw0;
#pragma unroll
        for (int it = 0; it < 64; it++) {
            int idx = tid + 256 * it;
            int kk = idx >> 7, p = idx & 127;
            sm[kk * XP + p] = src[(size_t)kk * HW + p];
        }
        __syncthreads();
        if (tid < 128) {
            for (int kk = 0; kk < 128; kk++) {
                float v = sm[kk * XP + tid];
                xxa = __fadd_rn(xxa, __fmul_rn(v, v));
                sxa = __fadd_rn(sxa, fabsf(v));
            }
        }
        int p = tid & 127;
#pragma unroll
        for (int it = 0; it < 8; it++) {
            int oct = (tid >> 7) * 8 + it;         // 0..15 within half
            float f[8];
#pragma unroll
            for (int j = 0; j < 8; j++) f[j] = sm[(oct * 8 + j) * XP + p];
            uint4 v;
            v.x = packbf(f[0], f[1]); v.y = packbf(f[2], f[3]);
            v.z = packbf(f[4], f[5]); v.w = packbf(f[6], f[7]);
            *(uint4 *)(dst + img_off(p, h * 16 + oct)) = v;
        }
        __syncthreads();
    }
    if (tid < 128) {
        g_xx[tile * 128 + tid] = xxa;
        g_sx[tile * 128 + tid] = sxa;
    }
}

// =====================================================================
// mma_kernel: warp-level bf16 HMMA, 128px x 1024 codes, 8 chunks of 128,
//   double-buffered B. Epilogue: running min + candidate superset.
//   Tail: cnt==1 -> finalize directly; cnt>1 -> enqueue for rescore.
// grid 512 x 256 (8 warps, 16 px each)
// =====================================================================
#define SM_WSQ 0
#define SM_CNT 4096
#define SM_A   8192
#define SM_B0  73728
#define SM_B1  139264
#define SMEM_MMA 204800

__device__ __forceinline__ void copy_img(uint32_t dst, const unsigned char *src, int tid) {
#pragma unroll
    for (int i = 0; i < 16; i++) {
        int c = tid + 256 * i;        // 4096 chunks of 16B
        cp16(dst + (uint32_t)c * 16u, src + (size_t)c * 16u);
    }
}

__global__ __launch_bounds__(256, 1) void mma_kernel(float *__restrict__ out_idxf) {
    extern __shared__ char smc[];
    uint32_t sb = smem_u32(smc);
    float *wsq_s = (float *)(smc + SM_WSQ);
    int *cnt_s = (int *)(smc + SM_CNT);
    const int tid = threadIdx.x, warp = tid >> 5, lane = tid & 31;
    const int tile = blockIdx.x;
    const int m0 = warp * 16;

    copy_img(sb + SM_A, g_xb + (size_t)tile * 65536, tid);
    copy_img(sb + SM_B0, g_wb, tid);
    CP_COMMIT();

    for (int i = tid; i < CODES; i += 256) wsq_s[i] = g_wsq[i];
    if (tid < 128) cnt_s[tid] = 0;
    if (tid == 0) {
        float m = 0.f;
        for (int i = 0; i < 128; i++) m = fmaxf(m, g_pmax[i]);
        ((float *)(smc + SM_CNT))[130] = m;   // stash wmax after counters
    }
    __syncthreads();
    const float wmax = ((float *)(smc + SM_CNT))[130];

    // per-thread pixel pair (D-frag rows): px0 = m0 + lane/4, px1 = px0+8
    const int pxl0 = m0 + (lane >> 2);
    const int pix0 = tile * 128 + pxl0;
    const float xx0 = g_xx[pix0], xx1 = g_xx[pix0 + 8];
    const float TH0 = __fmaf_rn(g_sx[pix0] * wmax, 0.0172f, 1e-3f);
    const float TH1 = __fmaf_rn(g_sx[pix0 + 8] * wmax, 0.0172f, 1e-3f);
    float runmin0 = __int_as_float(0x7f800000);
    float runmin1 = runmin0;

    // ldmatrix address bases (chunk-swizzled layout)
    const int mat = lane >> 3, r7 = lane & 7;
    const int a_row = m0 + r7 + ((mat & 1) << 3);
    const int a_cadd = mat >> 1;
    const uint32_t a_base = sb + SM_A + (uint32_t)a_row * 512u;
    const int b_rowoff = r7 + ((mat >> 1) << 3);
    const int b_cadd = mat & 1;

    for (int c = 0; c < NCHUNK; c++) {
        if (c < 7) {
            copy_img(sb + (((c + 1) & 1) ? SM_B1 : SM_B0), g_wb + (size_t)(c + 1) * 65536, tid);
            CP_COMMIT();
            CP_WAIT1();
        } else {
            CP_WAIT0();
        }
        __syncthreads();

        const uint32_t b_base = sb + ((c & 1) ? SM_B1 : SM_B0) + (uint32_t)b_rowoff * 512u;

        float acc[16][4];
#pragma unroll
        for (int nb = 0; nb < 16; nb++)
#pragma unroll
            for (int j = 0; j < 4; j++) acc[nb][j] = 0.f;

#pragma unroll
        for (int ks = 0; ks < 16; ks++) {
            uint32_t a0, a1, a2, a3;
            ldsm_x4(a0, a1, a2, a3, a_base + (uint32_t)(((2 * ks + a_cadd) ^ r7) << 4));
#pragma unroll
            for (int nbp = 0; nbp < 8; nbp++) {
                uint32_t b0, b1, b2, b3;
                ldsm_x4(b0, b1, b2, b3,
                        b_base + (uint32_t)(nbp * 8192) +
                        (uint32_t)(((2 * ks + b_cadd) ^ r7) << 4));
                mma16816(acc[2 * nbp], a0, a1, a2, a3, b0, b1);
                mma16816(acc[2 * nbp + 1], a0, a1, a2, a3, b2, b3);
            }
        }

        // ---- epilogue: scores, quad-min, threshold, candidate push ----
        const int code_base = c * 128 + 2 * (lane & 3);
        float lm0 = __int_as_float(0x7f800000), lm1 = lm0;
#pragma unroll
        for (int nb = 0; nb < 16; nb++) {
            const float *wq = wsq_s + c * 128 + nb * 8 + 2 * (lane & 3);
            float s;
            s = __fadd_rn(__fmaf_rn(-2.f, acc[nb][0], xx0), wq[0]); acc[nb][0] = s; lm0 = fminf(lm0, s);
            s = __fadd_rn(__fmaf_rn(-2.f, acc[nb][1], xx0), wq[1]); acc[nb][1] = s; lm0 = fminf(lm0, s);
            s = __fadd_rn(__fmaf_rn(-2.f, acc[nb][2], xx1), wq[0]); acc[nb][2] = s; lm1 = fminf(lm1, s);
            s = __fadd_rn(__fmaf_rn(-2.f, acc[nb][3], xx1), wq[1]); acc[nb][3] = s; lm1 = fminf(lm1, s);
        }
#pragma unroll
        for (int o = 1; o <= 2; o <<= 1) {
            lm0 = fminf(lm0, __shfl_xor_sync(0xffffffffu, lm0, o));
            lm1 = fminf(lm1, __shfl_xor_sync(0xffffffffu, lm1, o));
        }
        runmin0 = fminf(runmin0, lm0);
        runmin1 = fminf(runmin1, lm1);
        const float th0 = runmin0 + TH0, th1 = runmin1 + TH1;
#pragma unroll
        for (int nb = 0; nb < 16; nb++) {
            int cb = code_base + nb * 8;
            if (acc[nb][0] <= th0) {
                int sl = atomicAdd(&cnt_s[pxl0], 1);
                if (sl < 32) g_cand[(size_t)pix0 * 32 + sl] = cb;
            }
            if (acc[nb][1] <= th0) {
                int sl = atomicAdd(&cnt_s[pxl0], 1);
                if (sl < 32) g_cand[(size_t)pix0 * 32 + sl] = cb + 1;
            }
            if (acc[nb][2] <= th1) {
                int sl = atomicAdd(&cnt_s[pxl0 + 8], 1);
                if (sl < 32) g_cand[(size_t)(pix0 + 8) * 32 + sl] = cb;
            }
            if (acc[nb][3] <= th1) {
                int sl = atomicAdd(&cnt_s[pxl0 + 8], 1);
                if (sl < 32) g_cand[(size_t)(pix0 + 8) * 32 + sl] = cb + 1;
            }
        }
        __syncthreads();
    }

    // ---- tail: finalize cnt==1 pixels, enqueue the rest ----
    if (tid < 128) {
        int pix = tile * 128 + tid;
        int cnt = cnt_s[tid];
        g_cnt[pix] = cnt;
        if (cnt == 1) {
            int cidx = g_cand[(size_t)pix * 32];
            g_idx[pix] = cidx;
            out_idxf[pix] = (float)cidx;
        } else {
            int q = atomicAdd(&g_qcnt, 1);
            g_queue[q] = pix;
        }
    }
}

// =====================================================================
// rescore2: warp per queued pixel, one candidate per lane, exact fp32
//   chain (sequential ascending k, identical rounding). x loads are
//   warp-broadcast; w rows lane-private (L1/L2 hot).
// grid 512 x 256 (4096 warps, strided over queue)
// =====================================================================
__global__ __launch_bounds__(256) void rescore2(const float *__restrict__ x,
                                                const float *__restrict__ w,
                                                float *__restrict__ out_idxf) {
    const int lane = threadIdx.x & 31;
    const int gwarp = (blockIdx.x * blockDim.x + threadIdx.x) >> 5;
    const int nwarp = (gridDim.x * blockDim.x) >> 5;
    const int total = g_qcnt;
    const float INF = __int_as_float(0x7f800000);

    for (int q = gwarp; q < total; q += nwarp) {
        int pix = g_queue[q];
        int b = pix >> 10, hw = pix & 1023;
        int cnt = g_cnt[pix];
        float xxp = g_xx[pix];
        const float *xb = x + (size_t)b * CDIM * HW + hw;

        float bestd = INF;
        int besti = CODES;
        int nloop = (cnt > 32) ? 32 : 1;   // overflow -> stripe all 1024 codes

        for (int t = 0; t < nloop; t++) {
            int cidx;
            bool active;
            if (cnt > 32) { cidx = t * 32 + lane; active = true; }
            else          { cidx = (lane < cnt) ? g_cand[(size_t)pix * 32 + lane] : 0; active = (lane < cnt); }

            const float4 *wr = (const float4 *)(w + (size_t)cidx * CDIM);
            float dot = 0.f;
#pragma unroll 8
            for (int qq = 0; qq < 64; qq++) {
                float4 wv = wr[qq];
                dot = __fmaf_rn(xb[(size_t)(4 * qq + 0) * HW], wv.x, dot);
                dot = __fmaf_rn(xb[(size_t)(4 * qq + 1) * HW], wv.y, dot);
                dot = __fmaf_rn(xb[(size_t)(4 * qq + 2) * HW], wv.z, dot);
                dot = __fmaf_rn(xb[(size_t)(4 * qq + 3) * HW], wv.w, dot);
            }
            float d = __fadd_rn(__fmaf_rn(-2.f, dot, xxp), g_wsq[cidx]);
            if (active && (d < bestd || (d == bestd && cidx < besti))) { bestd = d; besti = cidx; }
        }
        // cross-lane reduce, tie -> smaller index
#pragma unroll
        for (int o = 16; o; o >>= 1) {
            float od = __shfl_xor_sync(0xffffffffu, bestd, o);
            int   oi = __shfl_xor_sync(0xffffffffu, besti, o);
            if (od < bestd || (od == bestd && oi < besti)) { bestd = od; besti = oi; }
        }
        if (lane == 0) {
            g_idx[pix] = besti;
            out_idxf[pix] = (float)besti;
        }
    }
}

// =====================================================================
// gather: quantized = weight[idx], ste = (q - x) + x
// =====================================================================
__global__ __launch_bounds__(256)
void gather_kernel(const float *__restrict__ x, const float *__restrict__ w,
                   float *__restrict__ out) {
    const int b = blockIdx.y;
    const int c0 = blockIdx.x * 32;
    const int hw4 = threadIdx.x * 4;

    int4 rows = *(const int4 *)&g_idx[b * HW + hw4];
    const float *xb = x + (size_t)b * CDIM * HW + hw4;
    float *qo = out + (size_t)b * CDIM * HW + hw4;
    float *so = out + (size_t)NPIX * CDIM + (size_t)b * CDIM * HW + hw4;
    const float *w0 = w + (size_t)rows.x * CDIM;
    const float *w1 = w + (size_t)rows.y * CDIM;
    const float *w2 = w + (size_t)rows.z * CDIM;
    const float *w3 = w + (size_t)rows.w * CDIM;

#pragma unroll 4
    for (int c = c0; c < c0 + 32; c++) {
        float4 qv;
        qv.x = w0[c]; qv.y = w1[c]; qv.z = w2[c]; qv.w = w3[c];
        float4 xv = *(const float4 *)(xb + (size_t)c * HW);
        *(float4 *)(qo + (size_t)c * HW) = qv;
        float4 sv;
        sv.x = __fadd_rn(__fsub_rn(qv.x, xv.x), xv.x);
        sv.y = __fadd_rn(__fsub_rn(qv.y, xv.y), xv.y);
        sv.z = __fadd_rn(__fsub_rn(qv.z, xv.z), xv.z);
        sv.w = __fadd_rn(__fsub_rn(qv.w, xv.w), xv.w);
        *(float4 *)(so + (size_t)c * HW) = sv;
    }
}

// =====================================================================
extern "C" void kernel_launch(void *const *d_in, const int *in_sizes, int n_in,
                              void *d_out, int out_size) {
    const float *x = (const float *)d_in[0];
    const float *w = (const float *)d_in[1];
    if (n_in >= 2 && in_sizes[0] == CODES * CDIM && in_sizes[1] == NPIX * CDIM) {
        const float *tmp = x; x = w; w = tmp;
    }
    float *out = (float *)d_out;
    float *out_idxf = out + 2 * (size_t)NPIX * CDIM;

    cudaFuncSetAttribute(prep_x, cudaFuncAttributeMaxDynamicSharedMemorySize, 128 * XP * 4);
    cudaFuncSetAttribute(mma_kernel, cudaFuncAttributeMaxDynamicSharedMemorySize, SMEM_MMA);

    prep_w<<<128, 256>>>(w);
    prep_x<<<512, 256, 128 * XP * 4>>>(x);
    mma_kernel<<<512, 256, SMEM_MMA>>>(out_idxf);
    rescore2<<<512, 256>>>(x, w, out_idxf);
    gather_kernel<<<dim3(8, 64), 256>>>(x, w, out);
}

// round 7
// speedup vs baseline: 1.4728x; 1.4728x over previous
#include <cuda_runtime.h>
#include <cuda_bf16.h>
#include <cstdint>

#define CODES 1024
#define CDIM  256
#define HW    1024
#define NPIX  65536
#define NCHUNK 8            // 1024 codes / 128
#define NTILE  512          // 65536 px / 128

// ---------------- static scratch ----------------
__device__ __align__(1024) unsigned char g_wb[NCHUNK * 65536]; // bf16 B images (swizzled)
__device__ __align__(1024) unsigned char g_xb[NTILE * 65536];  // bf16 A images (swizzled)
__device__ __align__(1024) float g_xT[(size_t)NPIX * CDIM];    // fp32 x, pixel-major (64MB)
__device__ float g_wsq[CODES];
__device__ float g_pmax[128];
__device__ float g_xx[NPIX];
__device__ float g_sx[NPIX];
__device__ int   g_cand[NPIX * 32];
__device__ int   g_cnt[NPIX];
__device__ int   g_idx[NPIX];
__device__ int   g_queue[NPIX];
__device__ int   g_qcnt;

// ---------------- helpers ----------------
__device__ __forceinline__ uint32_t smem_u32(const void *p) {
    uint32_t a;
    asm("{ .reg .u64 t; cvta.to.shared.u64 t, %1; cvt.u32.u64 %0, t; }" : "=r"(a) : "l"(p));
    return a;
}
__device__ __forceinline__ void cp16(uint32_t dst, const void *src) {
    asm volatile("cp.async.cg.shared.global [%0], [%1], 16;" :: "r"(dst), "l"(src) : "memory");
}
#define CP_COMMIT() asm volatile("cp.async.commit_group;" ::: "memory")
#define CP_WAIT1()  asm volatile("cp.async.wait_group 1;" ::: "memory")
#define CP_WAIT0()  asm volatile("cp.async.wait_group 0;" ::: "memory")

__device__ __forceinline__ uint32_t packbf(float lo, float hi) {
    uint32_t r;
    asm("cvt.rn.bf16x2.f32 %0, %1, %2;" : "=r"(r) : "f"(hi), "f"(lo));  // r = hi<<16 | lo
    return r;
}
// image layout: 128 rows x 256 bf16 k-major, rows of 512B = 32 16B-chunks,
// chunk swizzle: stored chunk index = chunk ^ (row & 7)  -> ldmatrix conflict-free
__device__ __forceinline__ uint32_t img_off(int row, int chunk) {
    return (uint32_t)row * 512u + (uint32_t)((chunk ^ (row & 7)) << 4);
}

__device__ __forceinline__ void ldsm_x4(uint32_t &r0, uint32_t &r1, uint32_t &r2, uint32_t &r3,
                                        uint32_t addr) {
    asm volatile("ldmatrix.sync.aligned.m8n8.x4.shared.b16 {%0,%1,%2,%3}, [%4];"
                 : "=r"(r0), "=r"(r1), "=r"(r2), "=r"(r3) : "r"(addr));
}
__device__ __forceinline__ void mma16816(float *d, uint32_t a0, uint32_t a1, uint32_t a2,
                                         uint32_t a3, uint32_t b0, uint32_t b1) {
    asm volatile("mma.sync.aligned.m16n8k16.row.col.f32.bf16.bf16.f32 "
                 "{%0,%1,%2,%3}, {%4,%5,%6,%7}, {%8,%9}, {%0,%1,%2,%3};"
                 : "+f"(d[0]), "+f"(d[1]), "+f"(d[2]), "+f"(d[3])
                 : "r"(a0), "r"(a1), "r"(a2), "r"(a3), "r"(b0), "r"(b1));
}

// =====================================================================
// prep_w: exact wsq, bf16 swizzled B images, per-block max|w|, zero queue
// grid 128 x 256 (8 codes/block, one warp per code)
// =====================================================================
__global__ void prep_w(const float *__restrict__ w) {
    __shared__ float wm[8];
    if (blockIdx.x == 0 && threadIdx.x == 0) g_qcnt = 0;
    int wid = threadIdx.x >> 5, lane = threadIdx.x & 31;
    int code = blockIdx.x * 8 + wid;
    const float *row = w + code * CDIM;
    float s = 0.f, pm = 0.f;
#pragma unroll
    for (int j = 0; j < 8; j++) {
        float v = row[lane + 32 * j];
        s = __fmaf_rn(v, v, s);
        pm = fmaxf(pm, fabsf(v));
    }
#pragma unroll
    for (int o = 16; o; o >>= 1) {
        s += __shfl_xor_sync(0xffffffffu, s, o);
        pm = fmaxf(pm, __shfl_xor_sync(0xffffffffu, pm, o));
    }
    if (lane == 0) { g_wsq[code] = s; wm[wid] = pm; }
    float f[8];
#pragma unroll
    for (int j = 0; j < 8; j++) f[j] = row[lane * 8 + j];
    uint4 v;
    v.x = packbf(f[0], f[1]); v.y = packbf(f[2], f[3]);
    v.z = packbf(f[4], f[5]); v.w = packbf(f[6], f[7]);
    int chunk = code >> 7, lr = code & 127;
    *(uint4 *)(g_wb + chunk * 65536 + img_off(lr, lane)) = v;
    __syncthreads();
    if (threadIdx.x == 0) {
        float m = 0.f;
        for (int i = 0; i < 8; i++) m = fmaxf(m, wm[i]);
        g_pmax[blockIdx.x] = m;
    }
}

// =====================================================================
// transpose_x: x[b][k][hw] -> g_xT[pix][k] fp32 (32x32 tiles, coalesced)
// grid (32, 8, 64) x 256
// =====================================================================
__global__ __launch_bounds__(256) void transpose_x(const float *__restrict__ x) {
    __shared__ float tile[32][33];
    int tx = threadIdx.x & 31, ty = threadIdx.x >> 5;
    int hw0 = blockIdx.x * 32, k0 = blockIdx.y * 32, b = blockIdx.z;
    const float *src = x + (size_t)b * CDIM * HW + (size_t)k0 * HW + hw0;
#pragma unroll
    for (int i = 0; i < 4; i++)
        tile[ty + 8 * i][tx] = src[(size_t)(ty + 8 * i) * HW + tx];
    __syncthreads();
    float *dst = g_xT + (size_t)(b * HW + hw0) * CDIM + k0;
#pragma unroll
    for (int i = 0; i < 4; i++)
        dst[(size_t)(ty + 8 * i) * CDIM + tx] = tile[tx][ty + 8 * i];
}

// =====================================================================
// prep_x: per 128-pixel tile: transpose+convert x -> bf16 swizzled A image,
//         exact sequential xx and sum|x|.  grid 512 x 256.
// =====================================================================
#define XP 130
__global__ __launch_bounds__(256) void prep_x(const float *__restrict__ x) {
    extern __shared__ float sm[];
    const int tile = blockIdx.x;
    const int b = tile >> 3, hw0 = (tile & 7) * 128;
    const int tid = threadIdx.x;
    unsigned char *dst = g_xb + (size_t)tile * 65536;
    float xxa = 0.f, sxa = 0.f;

    for (int h = 0; h < 2; h++) {
        const float *src = x + (size_t)b * CDIM * HW + (size_t)(h * 128) * HW + hw0;
#pragma unroll
        for (int it = 0; it < 64; it++) {
            int idx = tid + 256 * it;
            int kk = idx >> 7, p = idx & 127;
            sm[kk * XP + p] = src[(size_t)kk * HW + p];
        }
        __syncthreads();
        if (tid < 128) {
            for (int kk = 0; kk < 128; kk++) {
                float v = sm[kk * XP + tid];
                xxa = __fadd_rn(xxa, __fmul_rn(v, v));
                sxa = __fadd_rn(sxa, fabsf(v));
            }
        }
        int p = tid & 127;
#pragma unroll
        for (int it = 0; it < 8; it++) {
            int oct = (tid >> 7) * 8 + it;         // 0..15 within half
            float f[8];
#pragma unroll
            for (int j = 0; j < 8; j++) f[j] = sm[(oct * 8 + j) * XP + p];
            uint4 v;
            v.x = packbf(f[0], f[1]); v.y = packbf(f[2], f[3]);
            v.z = packbf(f[4], f[5]); v.w = packbf(f[6], f[7]);
            *(uint4 *)(dst + img_off(p, h * 16 + oct)) = v;
        }
        __syncthreads();
    }
    if (tid < 128) {
        g_xx[tile * 128 + tid] = xxa;
        g_sx[tile * 128 + tid] = sxa;
    }
}

// =====================================================================
// mma_kernel: warp-level bf16 HMMA, 128px x 1024 codes, 8 chunks of 128,
//   double-buffered B. Epilogue: running min + candidate superset.
//   Tail: cnt==1 -> finalize directly; cnt>1 -> enqueue for rescore.
// grid 512 x 256 (8 warps, 16 px each)
// =====================================================================
#define SM_WSQ 0
#define SM_CNT 4096
#define SM_A   8192
#define SM_B0  73728
#define SM_B1  139264
#define SMEM_MMA 204800

__device__ __forceinline__ void copy_img(uint32_t dst, const unsigned char *src, int tid) {
#pragma unroll
    for (int i = 0; i < 16; i++) {
        int c = tid + 256 * i;        // 4096 chunks of 16B
        cp16(dst + (uint32_t)c * 16u, src + (size_t)c * 16u);
    }
}

__global__ __launch_bounds__(256, 1) void mma_kernel(float *__restrict__ out_idxf) {
    extern __shared__ char smc[];
    uint32_t sb = smem_u32(smc);
    float *wsq_s = (float *)(smc + SM_WSQ);
    int *cnt_s = (int *)(smc + SM_CNT);
    const int tid = threadIdx.x, warp = tid >> 5, lane = tid & 31;
    const int tile = blockIdx.x;
    const int m0 = warp * 16;

    copy_img(sb + SM_A, g_xb + (size_t)tile * 65536, tid);
    copy_img(sb + SM_B0, g_wb, tid);
    CP_COMMIT();

    for (int i = tid; i < CODES; i += 256) wsq_s[i] = g_wsq[i];
    if (tid < 128) cnt_s[tid] = 0;
    if (tid == 0) {
        float m = 0.f;
        for (int i = 0; i < 128; i++) m = fmaxf(m, g_pmax[i]);
        ((float *)(smc + SM_CNT))[130] = m;   // stash wmax after counters
    }
    __syncthreads();
    const float wmax = ((float *)(smc + SM_CNT))[130];

    const int pxl0 = m0 + (lane >> 2);
    const int pix0 = tile * 128 + pxl0;
    const float xx0 = g_xx[pix0], xx1 = g_xx[pix0 + 8];
    const float TH0 = __fmaf_rn(g_sx[pix0] * wmax, 0.0172f, 1e-3f);
    const float TH1 = __fmaf_rn(g_sx[pix0 + 8] * wmax, 0.0172f, 1e-3f);
    float runmin0 = __int_as_float(0x7f800000);
    float runmin1 = runmin0;

    const int mat = lane >> 3, r7 = lane & 7;
    const int a_row = m0 + r7 + ((mat & 1) << 3);
    const int a_cadd = mat >> 1;
    const uint32_t a_base = sb + SM_A + (uint32_t)a_row * 512u;
    const int b_rowoff = r7 + ((mat >> 1) << 3);
    const int b_cadd = mat & 1;

    for (int c = 0; c < NCHUNK; c++) {
        if (c < 7) {
            copy_img(sb + (((c + 1) & 1) ? SM_B1 : SM_B0), g_wb + (size_t)(c + 1) * 65536, tid);
            CP_COMMIT();
            CP_WAIT1();
        } else {
            CP_WAIT0();
        }
        __syncthreads();

        const uint32_t b_base = sb + ((c & 1) ? SM_B1 : SM_B0) + (uint32_t)b_rowoff * 512u;

        float acc[16][4];
#pragma unroll
        for (int nb = 0; nb < 16; nb++)
#pragma unroll
            for (int j = 0; j < 4; j++) acc[nb][j] = 0.f;

#pragma unroll
        for (int ks = 0; ks < 16; ks++) {
            uint32_t a0, a1, a2, a3;
            ldsm_x4(a0, a1, a2, a3, a_base + (uint32_t)(((2 * ks + a_cadd) ^ r7) << 4));
#pragma unroll
            for (int nbp = 0; nbp < 8; nbp++) {
                uint32_t b0, b1, b2, b3;
                ldsm_x4(b0, b1, b2, b3,
                        b_base + (uint32_t)(nbp * 8192) +
                        (uint32_t)(((2 * ks + b_cadd) ^ r7) << 4));
                mma16816(acc[2 * nbp], a0, a1, a2, a3, b0, b1);
                mma16816(acc[2 * nbp + 1], a0, a1, a2, a3, b2, b3);
            }
        }

        const int code_base = c * 128 + 2 * (lane & 3);
        float lm0 = __int_as_float(0x7f800000), lm1 = lm0;
#pragma unroll
        for (int nb = 0; nb < 16; nb++) {
            const float *wq = wsq_s + c * 128 + nb * 8 + 2 * (lane & 3);
            float s;
            s = __fadd_rn(__fmaf_rn(-2.f, acc[nb][0], xx0), wq[0]); acc[nb][0] = s; lm0 = fminf(lm0, s);
            s = __fadd_rn(__fmaf_rn(-2.f, acc[nb][1], xx0), wq[1]); acc[nb][1] = s; lm0 = fminf(lm0, s);
            s = __fadd_rn(__fmaf_rn(-2.f, acc[nb][2], xx1), wq[0]); acc[nb][2] = s; lm1 = fminf(lm1, s);
            s = __fadd_rn(__fmaf_rn(-2.f, acc[nb][3], xx1), wq[1]); acc[nb][3] = s; lm1 = fminf(lm1, s);
        }
#pragma unroll
        for (int o = 1; o <= 2; o <<= 1) {
            lm0 = fminf(lm0, __shfl_xor_sync(0xffffffffu, lm0, o));
            lm1 = fminf(lm1, __shfl_xor_sync(0xffffffffu, lm1, o));
        }
        runmin0 = fminf(runmin0, lm0);
        runmin1 = fminf(runmin1, lm1);
        const float th0 = runmin0 + TH0, th1 = runmin1 + TH1;
#pragma unroll
        for (int nb = 0; nb < 16; nb++) {
            int cb = code_base + nb * 8;
            if (acc[nb][0] <= th0) {
                int sl = atomicAdd(&cnt_s[pxl0], 1);
                if (sl < 32) g_cand[(size_t)pix0 * 32 + sl] = cb;
            }
            if (acc[nb][1] <= th0) {
                int sl = atomicAdd(&cnt_s[pxl0], 1);
                if (sl < 32) g_cand[(size_t)pix0 * 32 + sl] = cb + 1;
            }
            if (acc[nb][2] <= th1) {
                int sl = atomicAdd(&cnt_s[pxl0 + 8], 1);
                if (sl < 32) g_cand[(size_t)(pix0 + 8) * 32 + sl] = cb;
            }
            if (acc[nb][3] <= th1) {
                int sl = atomicAdd(&cnt_s[pxl0 + 8], 1);
                if (sl < 32) g_cand[(size_t)(pix0 + 8) * 32 + sl] = cb + 1;
            }
        }
        __syncthreads();
    }

    if (tid < 128) {
        int pix = tile * 128 + tid;
        int cnt = cnt_s[tid];
        g_cnt[pix] = cnt;
        if (cnt == 1) {
            int cidx = g_cand[(size_t)pix * 32];
            g_idx[pix] = cidx;
            out_idxf[pix] = (float)cidx;
        } else {
            int q = atomicAdd(&g_qcnt, 1);
            g_queue[q] = pix;
        }
    }
}

// =====================================================================
// rescore2: warp per queued pixel, one candidate per lane, exact fp32
//   chain (sequential ascending k). x from pixel-major g_xT: 64 contiguous
//   broadcast float4 loads (8 lines/pixel). w rows lane-private, L2-hot.
// grid 512 x 256 (4096 warps, strided over queue)
// =====================================================================
__global__ __launch_bounds__(256) void rescore2(const float *__restrict__ w,
                                                float *__restrict__ out_idxf) {
    const int lane = threadIdx.x & 31;
    const int gwarp = (blockIdx.x * blockDim.x + threadIdx.x) >> 5;
    const int nwarp = (gridDim.x * blockDim.x) >> 5;
    const int total = g_qcnt;
    const float INF = __int_as_float(0x7f800000);

    for (int q = gwarp; q < total; q += nwarp) {
        int pix = g_queue[q];
        int cnt = g_cnt[pix];
        float xxp = g_xx[pix];
        const float4 *xb4 = (const float4 *)(g_xT + (size_t)pix * CDIM);

        float bestd = INF;
        int besti = CODES;
        int nloop = (cnt > 32) ? 32 : 1;   // overflow -> stripe all 1024 codes

        for (int t = 0; t < nloop; t++) {
            int cidx;
            bool active;
            if (cnt > 32) { cidx = t * 32 + lane; active = true; }
            else          { cidx = (lane < cnt) ? g_cand[(size_t)pix * 32 + lane] : 0; active = (lane < cnt); }

            const float4 *wr = (const float4 *)(w + (size_t)cidx * CDIM);
            float dot = 0.f;
#pragma unroll 8
            for (int qq = 0; qq < 64; qq++) {
                float4 wv = wr[qq];
                float4 xv = xb4[qq];
                dot = __fmaf_rn(xv.x, wv.x, dot);
                dot = __fmaf_rn(xv.y, wv.y, dot);
                dot = __fmaf_rn(xv.z, wv.z, dot);
                dot = __fmaf_rn(xv.w, wv.w, dot);
            }
            float d = __fadd_rn(__fmaf_rn(-2.f, dot, xxp), g_wsq[cidx]);
            if (active && (d < bestd || (d == bestd && cidx < besti))) { bestd = d; besti = cidx; }
        }
#pragma unroll
        for (int o = 16; o; o >>= 1) {
            float od = __shfl_xor_sync(0xffffffffu, bestd, o);
            int   oi = __shfl_xor_sync(0xffffffffu, besti, o);
            if (od < bestd || (od == bestd && oi < besti)) { bestd = od; besti = oi; }
        }
        if (lane == 0) {
            g_idx[pix] = besti;
            out_idxf[pix] = (float)besti;
        }
    }
}

// =====================================================================
// gather: quantized = weight[idx], ste = (q - x) + x
// =====================================================================
__global__ __launch_bounds__(256)
void gather_kernel(const float *__restrict__ x, const float *__restrict__ w,
                   float *__restrict__ out) {
    const int b = blockIdx.y;
    const int c0 = blockIdx.x * 32;
    const int hw4 = threadIdx.x * 4;

    int4 rows = *(const int4 *)&g_idx[b * HW + hw4];
    const float *xb = x + (size_t)b * CDIM * HW + hw4;
    float *qo = out + (size_t)b * CDIM * HW + hw4;
    float *so = out + (size_t)NPIX * CDIM + (size_t)b * CDIM * HW + hw4;
    const float *w0 = w + (size_t)rows.x * CDIM;
    const float *w1 = w + (size_t)rows.y * CDIM;
    const float *w2 = w + (size_t)rows.z * CDIM;
    const float *w3 = w + (size_t)rows.w * CDIM;

#pragma unroll 4
    for (int c = c0; c < c0 + 32; c++) {
        float4 qv;
        qv.x = w0[c]; qv.y = w1[c]; qv.z = w2[c]; qv.w = w3[c];
        float4 xv = *(const float4 *)(xb + (size_t)c * HW);
        *(float4 *)(qo + (size_t)c * HW) = qv;
        float4 sv;
        sv.x = __fadd_rn(__fsub_rn(qv.x, xv.x), xv.x);
        sv.y = __fadd_rn(__fsub_rn(qv.y, xv.y), xv.y);
        sv.z = __fadd_rn(__fsub_rn(qv.z, xv.z), xv.z);
        sv.w = __fadd_rn(__fsub_rn(qv.w, xv.w), xv.w);
        *(float4 *)(so + (size_t)c * HW) = sv;
    }
}

// =====================================================================
extern "C" void kernel_launch(void *const *d_in, const int *in_sizes, int n_in,
                              void *d_out, int out_size) {
    const float *x = (const float *)d_in[0];
    const float *w = (const float *)d_in[1];
    if (n_in >= 2 && in_sizes[0] == CODES * CDIM && in_sizes[1] == NPIX * CDIM) {
        const float *tmp = x; x = w; w = tmp;
    }
    float *out = (float *)d_out;
    float *out_idxf = out + 2 * (size_t)NPIX * CDIM;

    cudaFuncSetAttribute(prep_x, cudaFuncAttributeMaxDynamicSharedMemorySize, 128 * XP * 4);
    cudaFuncSetAttribute(mma_kernel, cudaFuncAttributeMaxDynamicSharedMemorySize, SMEM_MMA);

    prep_w<<<128, 256>>>(w);
    prep_x<<<512, 256, 128 * XP * 4>>>(x);
    transpose_x<<<dim3(32, 8, 64), 256>>>(x);
    mma_kernel<<<512, 256, SMEM_MMA>>>(out_idxf);
    rescore2<<<512, 256>>>(w, out_idxf);
    gather_kernel<<<dim3(8, 64), 256>>>(x, w, out);
}